// round 2
// baseline (speedup 1.0000x reference)
#include <cuda_runtime.h>

// Shapes: field/gt_field (8,4,64,128,64) f32, ct/gt_ct (8,1) f32, sdf (8,1,64,128,64) f32.
// Output: scalar f32 total loss. Single fused kernel, float4 along W, last-block finalize.

#define NB 8
#define ND 64
#define NH 128
#define NW 64
#define SP (ND*NH*NW)          // 524288 spatial per (batch,channel)
#define CS SP
#define NPTS (NB*SP)           // 4194304
#define NVEC (NPTS/4)          // 1048576 float4 quads
#define NBLK (NVEC/256)        // 4096 blocks

#define DXd ((2.0 + 0.5) / 63.0)
#define DYd ((0.5 + 0.5) / 127.0)
#define DZd ((0.3 + 0.5) / 63.0)

__device__ __constant__ float c_inv2dx = (float)(1.0 / (2.0 * DXd));
__device__ __constant__ float c_inv2dy = (float)(1.0 / (2.0 * DYd));
__device__ __constant__ float c_inv2dz = (float)(1.0 / (2.0 * DZd));
__device__ __constant__ float c_idx2   = (float)(1.0 / (DXd * DXd));
__device__ __constant__ float c_idy2   = (float)(1.0 / (DYd * DYd));
__device__ __constant__ float c_idz2   = (float)(1.0 / (DZd * DZd));

__device__ __constant__ float c_sc_field  = (float)(1.0  / (double)(NB*4*SP));
__device__ __constant__ float c_sc_ct     = (float)(10.0 / 8.0);
__device__ __constant__ float c_sc_cm     = (float)(1.0  / (double)(NB*(ND-2)*(NH-2)*(NW-2))); // cont & mom share
__device__ __constant__ float c_sc_noslip = (float)(10.0 / (double)NPTS);
__device__ __constant__ float c_sc_inlet  = (float)(5.0  / (double)(NB*ND*NH));
__device__ __constant__ float c_sc_outlet = (float)(1.0  / (double)(NB*ND*NH));

#define INV_RE 1.0e-6f

__device__ double g_acc = 0.0;
__device__ unsigned int g_count = 0;

__device__ __forceinline__ float4 ld4(const float* p) {
    return *reinterpret_cast<const float4*>(p);
}
__device__ __forceinline__ void unp(float4 t, float* a) {
    a[0] = t.x; a[1] = t.y; a[2] = t.z; a[3] = t.w;
}

__global__ void __launch_bounds__(256) k_loss(
    const float* __restrict__ field,
    const float* __restrict__ ct,
    const float* __restrict__ gt_field,
    const float* __restrict__ gt_ct,
    const float* __restrict__ sdf,
    float* __restrict__ out)
{
    const int vid = blockIdx.x * 256 + threadIdx.x;   // exactly NVEC threads
    const int wq = vid & 15;              // quad index along W
    const int h  = (vid >> 4)  & (NH - 1);
    const int d  = (vid >> 11) & (ND - 1);
    const int b  = vid >> 17;
    const int w0 = wq << 2;               // first w of this quad

    const int sidx  = (d * NH + h) * NW + w0;
    const float* fb = field    + b * (4 * SP) + sidx;
    const float* gb = gt_field + b * (4 * SP) + sidx;

    float acc = 0.0f;

    if (vid < 8) {
        float dct = ct[vid] - gt_ct[vid];
        acc += c_sc_ct * dct * dct;
    }

    // center vectors, 4 channels (u,v,w,p)
    float Fv[4][4];
    #pragma unroll
    for (int c = 0; c < 4; c++) unp(ld4(fb + c * CS), Fv[c]);

    // field MSE (consumes gt immediately)
    {
        float m = 0.0f;
        #pragma unroll
        for (int c = 0; c < 4; c++) {
            float Gv[4]; unp(ld4(gb + c * CS), Gv);
            #pragma unroll
            for (int l = 0; l < 4; l++) {
                float dd = Fv[c][l] - Gv[l];
                m += dd * dd;
            }
        }
        acc += c_sc_field * m;
    }

    float Sv[4]; unp(ld4(sdf + b * SP + sidx), Sv);

    // no-slip (sdf <= 0), all points
    {
        float m = 0.0f;
        #pragma unroll
        for (int l = 0; l < 4; l++) {
            if (Sv[l] <= 0.0f)
                m += Fv[0][l]*Fv[0][l] + Fv[1][l]*Fv[1][l] + Fv[2][l]*Fv[2][l];
        }
        acc += c_sc_noslip * m;
    }

    // inlet: w==0 is lane 0 of quad 0
    if (wq == 0) {
        float du0 = Fv[0][0] - 1.0f;
        acc += c_sc_inlet * (du0 * du0 + Fv[1][0]*Fv[1][0] + Fv[2][0]*Fv[2][0]);
    }

    // outlet: w==63 vs w==62 are lanes 3,2 of quad 15 — intra-vector
    if (wq == 15) {
        float a0 = Fv[0][3] - Fv[0][2];
        float a1 = Fv[1][3] - Fv[1][2];
        float a2 = Fv[2][3] - Fv[2][2];
        acc += c_sc_outlet * (a0*a0 + a1*a1 + a2*a2);
    }

    // interior continuity + momentum
    if (d >= 1 && d <= ND - 2 && h >= 1 && h <= NH - 2) {
        const int OY = NW;
        const int OZ = NH * NW;

        float Yp[4][4], Ym[4][4], Zp[4][4], Zm[4][4];
        #pragma unroll
        for (int c = 0; c < 4; c++) {
            unp(ld4(fb + c * CS + OY), Yp[c]);
            unp(ld4(fb + c * CS - OY), Ym[c]);
            unp(ld4(fb + c * CS + OZ), Zp[c]);
            unp(ld4(fb + c * CS - OZ), Zm[c]);
        }

        // x edge scalars (guarded: quad 0 has no left neighbor, quad 15 no right)
        float Lc[4] = {0,0,0,0}, Rc[4] = {0,0,0,0};
        if (wq != 0) {
            #pragma unroll
            for (int c = 0; c < 4; c++) Lc[c] = fb[c * CS - 1];
        }
        if (wq != 15) {
            #pragma unroll
            for (int c = 0; c < 4; c++) Rc[c] = fb[c * CS + 4];
        }

        float msum = 0.0f;
        #pragma unroll
        for (int l = 0; l < 4; l++) {
            const int wg = w0 + l;
            if (wg >= 1 && wg <= NW - 2 && Sv[l] > 0.0f) {
                float xm[4], xp[4];
                #pragma unroll
                for (int c = 0; c < 4; c++) {
                    xm[c] = (l == 0) ? Lc[c] : Fv[c][l - 1];
                    xp[c] = (l == 3) ? Rc[c] : Fv[c][l + 1];
                }

                const float u  = Fv[0][l], v = Fv[1][l], wv = Fv[2][l];

                float du_dx = (xp[0] - xm[0]) * c_inv2dx;
                float dv_dx = (xp[1] - xm[1]) * c_inv2dx;
                float dw_dx = (xp[2] - xm[2]) * c_inv2dx;
                float dp_dx = (xp[3] - xm[3]) * c_inv2dx;

                float du_dy = (Yp[0][l] - Ym[0][l]) * c_inv2dy;
                float dv_dy = (Yp[1][l] - Ym[1][l]) * c_inv2dy;
                float dw_dy = (Yp[2][l] - Ym[2][l]) * c_inv2dy;
                float dp_dy = (Yp[3][l] - Ym[3][l]) * c_inv2dy;

                float du_dz = (Zp[0][l] - Zm[0][l]) * c_inv2dz;
                float dv_dz = (Zp[1][l] - Zm[1][l]) * c_inv2dz;
                float dw_dz = (Zp[2][l] - Zm[2][l]) * c_inv2dz;
                float dp_dz = (Zp[3][l] - Zm[3][l]) * c_inv2dz;

                float div = du_dx + dv_dy + dw_dz;
                msum += div * div;

                float lap_u = (xp[0]    - 2.0f*u  + xm[0])    * c_idx2
                            + (Yp[0][l] - 2.0f*u  + Ym[0][l]) * c_idy2
                            + (Zp[0][l] - 2.0f*u  + Zm[0][l]) * c_idz2;
                float lap_v = (xp[1]    - 2.0f*v  + xm[1])    * c_idx2
                            + (Yp[1][l] - 2.0f*v  + Ym[1][l]) * c_idy2
                            + (Zp[1][l] - 2.0f*v  + Zm[1][l]) * c_idz2;
                float lap_w = (xp[2]    - 2.0f*wv + xm[2])    * c_idx2
                            + (Yp[2][l] - 2.0f*wv + Ym[2][l]) * c_idy2
                            + (Zp[2][l] - 2.0f*wv + Zm[2][l]) * c_idz2;

                float rx = u*du_dx + v*du_dy + wv*du_dz + dp_dx - INV_RE*lap_u;
                float ry = u*dv_dx + v*dv_dy + wv*dv_dz + dp_dy - INV_RE*lap_v;
                float rz = u*dw_dx + v*dw_dy + wv*dw_dz + dp_dz - INV_RE*lap_w;

                msum += rx*rx + ry*ry + rz*rz;
            }
        }
        acc += c_sc_cm * msum;
    }

    // ---- reduction: warp shfl (f32) -> block (f64) -> global atomic (f64) ----
    #pragma unroll
    for (int o = 16; o > 0; o >>= 1)
        acc += __shfl_down_sync(0xffffffffu, acc, o);

    __shared__ double warpsum[8];
    if ((threadIdx.x & 31) == 0)
        warpsum[threadIdx.x >> 5] = (double)acc;
    __syncthreads();

    if (threadIdx.x == 0) {
        double t = 0.0;
        #pragma unroll
        for (int i = 0; i < 8; i++) t += warpsum[i];
        atomicAdd(&g_acc, t);
        __threadfence();
        unsigned int ticket = atomicAdd(&g_count, 1u);
        if (ticket == (unsigned)(gridDim.x - 1)) {
            // last block: all prior atomics to g_acc are visible
            double tot = atomicAdd(&g_acc, 0.0);
            out[0] = (float)tot;
            // reset for next (graph-replayed) invocation — deterministic
            g_acc = 0.0;
            g_count = 0u;
            __threadfence();
        }
    }
}

extern "C" void kernel_launch(void* const* d_in, const int* in_sizes, int n_in,
                              void* d_out, int out_size)
{
    const float* field    = (const float*)d_in[0];
    const float* ct       = (const float*)d_in[1];
    const float* gt_field = (const float*)d_in[2];
    const float* gt_ct    = (const float*)d_in[3];
    const float* sdf      = (const float*)d_in[4];

    k_loss<<<NBLK, 256>>>(field, ct, gt_field, gt_ct, sdf, (float*)d_out);
}

// round 3
// speedup vs baseline: 1.2228x; 1.2228x over previous
#include <cuda_runtime.h>

// Shapes: field/gt_field (8,4,64,128,64) f32, ct/gt_ct (8,1) f32, sdf (8,1,64,128,64) f32.
// Output: scalar f32 total loss. Single fused kernel, float4 along W,
// channel-streamed interior (low register pressure), last-block finalize.

#define NB 8
#define ND 64
#define NH 128
#define NW 64
#define SP (ND*NH*NW)
#define CS SP
#define NPTS (NB*SP)
#define NVEC (NPTS/4)          // 1048576 float4 quads
#define NBLK (NVEC/256)        // 4096 blocks

#define DXd ((2.0 + 0.5) / 63.0)
#define DYd ((0.5 + 0.5) / 127.0)
#define DZd ((0.3 + 0.5) / 63.0)

__device__ __constant__ float c_inv2dx = (float)(1.0 / (2.0 * DXd));
__device__ __constant__ float c_inv2dy = (float)(1.0 / (2.0 * DYd));
__device__ __constant__ float c_inv2dz = (float)(1.0 / (2.0 * DZd));
__device__ __constant__ float c_idx2   = (float)(1.0 / (DXd * DXd));
__device__ __constant__ float c_idy2   = (float)(1.0 / (DYd * DYd));
__device__ __constant__ float c_idz2   = (float)(1.0 / (DZd * DZd));

__device__ __constant__ float c_sc_field  = (float)(1.0  / (double)(NB*4*SP));
__device__ __constant__ float c_sc_ct     = (float)(10.0 / 8.0);
__device__ __constant__ float c_sc_cm     = (float)(1.0  / (double)(NB*(ND-2)*(NH-2)*(NW-2)));
__device__ __constant__ float c_sc_noslip = (float)(10.0 / (double)NPTS);
__device__ __constant__ float c_sc_inlet  = (float)(5.0  / (double)(NB*ND*NH));
__device__ __constant__ float c_sc_outlet = (float)(1.0  / (double)(NB*ND*NH));

#define INV_RE 1.0e-6f
#define OY NW
#define OZ (NH*NW)

__device__ double g_acc = 0.0;
__device__ unsigned int g_count = 0;

__device__ __forceinline__ float4 ld4(const float* p) {
    return *reinterpret_cast<const float4*>(p);
}

__global__ void __launch_bounds__(256, 3) k_loss(
    const float* __restrict__ field,
    const float* __restrict__ ct,
    const float* __restrict__ gt_field,
    const float* __restrict__ gt_ct,
    const float* __restrict__ sdf,
    float* __restrict__ out)
{
    const int vid = blockIdx.x * 256 + threadIdx.x;   // exactly NVEC threads
    const int wq = vid & 15;
    const int h  = (vid >> 4)  & (NH - 1);
    const int d  = (vid >> 11) & (ND - 1);
    const int b  = vid >> 17;

    const int sidx  = ((d * NH + h) << 6) + (wq << 2);
    const float* fb = field    + b * (4 * SP) + sidx;
    const float* gb = gt_field + b * (4 * SP) + sidx;

    float acc = 0.0f;

    if (vid < 8) {
        float dct = ct[vid] - gt_ct[vid];
        acc += c_sc_ct * dct * dct;
    }

    // centers: Fv[c][lane]
    float Fv[4][4];
    #pragma unroll
    for (int c = 0; c < 4; c++) {
        float4 t = ld4(fb + c * CS);
        Fv[c][0] = t.x; Fv[c][1] = t.y; Fv[c][2] = t.z; Fv[c][3] = t.w;
    }

    // field MSE (gt consumed immediately)
    {
        float m = 0.0f;
        #pragma unroll
        for (int c = 0; c < 4; c++) {
            float4 g = ld4(gb + c * CS);
            float d0 = Fv[c][0] - g.x, d1 = Fv[c][1] - g.y;
            float d2 = Fv[c][2] - g.z, d3 = Fv[c][3] - g.w;
            m += d0*d0 + d1*d1 + d2*d2 + d3*d3;
        }
        acc += c_sc_field * m;
    }

    float4 sv = ld4(sdf + b * SP + sidx);
    float Sv[4] = {sv.x, sv.y, sv.z, sv.w};

    // no-slip (sdf <= 0)
    {
        float m = 0.0f;
        #pragma unroll
        for (int l = 0; l < 4; l++) {
            float q = Fv[0][l]*Fv[0][l] + Fv[1][l]*Fv[1][l] + Fv[2][l]*Fv[2][l];
            m += (Sv[l] <= 0.0f) ? q : 0.0f;
        }
        acc += c_sc_noslip * m;
    }

    // inlet: w==0 = lane0 of quad 0
    if (wq == 0) {
        float du0 = Fv[0][0] - 1.0f;
        acc += c_sc_inlet * (du0*du0 + Fv[1][0]*Fv[1][0] + Fv[2][0]*Fv[2][0]);
    }
    // outlet: w==63 vs 62 = lanes 3,2 of quad 15
    if (wq == 15) {
        float a0 = Fv[0][3] - Fv[0][2];
        float a1 = Fv[1][3] - Fv[1][2];
        float a2 = Fv[2][3] - Fv[2][2];
        acc += c_sc_outlet * (a0*a0 + a1*a1 + a2*a2);
    }

    // interior continuity + momentum, channel-streamed
    if (d >= 1 && d <= ND - 2 && h >= 1 && h <= NH - 2) {
        // lane weight: w-interior AND fluid
        float wgt[4];
        wgt[0] = (wq != 0  && Sv[0] > 0.0f) ? 1.0f : 0.0f;
        wgt[1] = (Sv[1] > 0.0f) ? 1.0f : 0.0f;
        wgt[2] = (Sv[2] > 0.0f) ? 1.0f : 0.0f;
        wgt[3] = (wq != 15 && Sv[3] > 0.0f) ? 1.0f : 0.0f;

        // --- pressure gradients first (no laplacian needed) ---
        float gpx[4], gpy[4], gpz[4];
        {
            const float* cb = fb + 3 * CS;
            float Lc = (wq != 0)  ? cb[-1] : 0.0f;
            float Rc = (wq != 15) ? cb[4]  : 0.0f;
            float4 yp = ld4(cb + OY), ym = ld4(cb - OY);
            gpy[0] = (yp.x - ym.x) * c_inv2dy;
            gpy[1] = (yp.y - ym.y) * c_inv2dy;
            gpy[2] = (yp.z - ym.z) * c_inv2dy;
            gpy[3] = (yp.w - ym.w) * c_inv2dy;
            float4 zp = ld4(cb + OZ), zm = ld4(cb - OZ);
            gpz[0] = (zp.x - zm.x) * c_inv2dz;
            gpz[1] = (zp.y - zm.y) * c_inv2dz;
            gpz[2] = (zp.z - zm.z) * c_inv2dz;
            gpz[3] = (zp.w - zm.w) * c_inv2dz;
            gpx[0] = (Fv[3][1] - Lc)       * c_inv2dx;
            gpx[1] = (Fv[3][2] - Fv[3][0]) * c_inv2dx;
            gpx[2] = (Fv[3][3] - Fv[3][1]) * c_inv2dx;
            gpx[3] = (Rc       - Fv[3][2]) * c_inv2dx;
        }

        float div[4] = {0.0f, 0.0f, 0.0f, 0.0f};
        float msum = 0.0f;

        // --- stream velocity channels u,v,w ---
        #pragma unroll
        for (int c = 0; c < 3; c++) {
            const float* cb = fb + c * CS;
            float Lc = (wq != 0)  ? cb[-1] : 0.0f;
            float Rc = (wq != 15) ? cb[4]  : 0.0f;

            float gy[4], sy[4];
            {
                float4 yp = ld4(cb + OY), ym = ld4(cb - OY);
                gy[0] = (yp.x - ym.x) * c_inv2dy; sy[0] = yp.x + ym.x;
                gy[1] = (yp.y - ym.y) * c_inv2dy; sy[1] = yp.y + ym.y;
                gy[2] = (yp.z - ym.z) * c_inv2dy; sy[2] = yp.z + ym.z;
                gy[3] = (yp.w - ym.w) * c_inv2dy; sy[3] = yp.w + ym.w;
            }
            float gz[4], sz[4];
            {
                float4 zp = ld4(cb + OZ), zm = ld4(cb - OZ);
                gz[0] = (zp.x - zm.x) * c_inv2dz; sz[0] = zp.x + zm.x;
                gz[1] = (zp.y - zm.y) * c_inv2dz; sz[1] = zp.y + zm.y;
                gz[2] = (zp.z - zm.z) * c_inv2dz; sz[2] = zp.z + zm.z;
                gz[3] = (zp.w - zm.w) * c_inv2dz; sz[3] = zp.w + zm.w;
            }

            #pragma unroll
            for (int l = 0; l < 4; l++) {
                float ce = Fv[c][l];
                float xm = (l == 0) ? Lc : Fv[c][l - 1];
                float xp = (l == 3) ? Rc : Fv[c][l + 1];
                float gx = (xp - xm) * c_inv2dx;
                float lap = (xp + xm - 2.0f * ce) * c_idx2
                          + (sy[l]   - 2.0f * ce) * c_idy2
                          + (sz[l]   - 2.0f * ce) * c_idz2;
                float gp  = (c == 0) ? gpx[l] : (c == 1) ? gpy[l] : gpz[l];
                float res = Fv[0][l] * gx + Fv[1][l] * gy[l] + Fv[2][l] * gz[l]
                          + gp - INV_RE * lap;
                msum   += wgt[l] * res * res;
                div[l] += (c == 0) ? gx : (c == 1) ? gy[l] : gz[l];
            }
        }

        #pragma unroll
        for (int l = 0; l < 4; l++)
            msum += wgt[l] * div[l] * div[l];

        acc += c_sc_cm * msum;
    }

    // ---- reduction: warp shfl (f32) -> block (f64) -> global atomic ----
    #pragma unroll
    for (int o = 16; o > 0; o >>= 1)
        acc += __shfl_down_sync(0xffffffffu, acc, o);

    __shared__ double warpsum[8];
    if ((threadIdx.x & 31) == 0)
        warpsum[threadIdx.x >> 5] = (double)acc;
    __syncthreads();

    if (threadIdx.x == 0) {
        double t = 0.0;
        #pragma unroll
        for (int i = 0; i < 8; i++) t += warpsum[i];
        atomicAdd(&g_acc, t);
        __threadfence();
        unsigned int ticket = atomicAdd(&g_count, 1u);
        if (ticket == (unsigned)(gridDim.x - 1)) {
            double tot = atomicAdd(&g_acc, 0.0);
            out[0] = (float)tot;
            g_acc = 0.0;       // reset for next graph replay
            g_count = 0u;
            __threadfence();
        }
    }
}

extern "C" void kernel_launch(void* const* d_in, const int* in_sizes, int n_in,
                              void* d_out, int out_size)
{
    const float* field    = (const float*)d_in[0];
    const float* ct       = (const float*)d_in[1];
    const float* gt_field = (const float*)d_in[2];
    const float* gt_ct    = (const float*)d_in[3];
    const float* sdf      = (const float*)d_in[4];

    k_loss<<<NBLK, 256>>>(field, ct, gt_field, gt_ct, sdf, (float*)d_out);
}